// round 1
// baseline (speedup 1.0000x reference)
#include <cuda_runtime.h>

// Problem constants (fixed by the dataset)
#define D        64
#define N_NODES  100000
#define E_EDGES  800000
#define NC_NODES 500
#define EC_EDGES 20000
#define HP       6

// Static scratch (no allocation allowed)
__device__ float g_w[E_EDGES];        // exp(fin_score) per main edge
__device__ float g_cw[EC_EDGES];      // exp(score_c) per cat edge
__device__ float g_denom[N_NODES];    // softmax denominator per dst node
__device__ float g_cdenom[NC_NODES];  // softmax denominator per cat dst
__device__ float g_trel[HP * D];      // precomputed time_rel per hour id

// ---------------------------------------------------------------------------
// Zero init: d_out (rst + cat_hid) and the two denominator arrays
__global__ void zero_kernel(float* __restrict__ out, int n_out) {
    int stride = gridDim.x * blockDim.x;
    for (int j = blockIdx.x * blockDim.x + threadIdx.x; j < n_out; j += stride)
        out[j] = 0.f;
    for (int j = blockIdx.x * blockDim.x + threadIdx.x; j < N_NODES; j += stride)
        g_denom[j] = 0.f;
    for (int j = blockIdx.x * blockDim.x + threadIdx.x; j < NC_NODES; j += stride)
        g_cdenom[j] = 0.f;
}

// ---------------------------------------------------------------------------
// Precompute time_rel for the 6 possible hour ids:
//   mix = (hour_emb[h-1] + hour_emb[h] + hour_emb[h+1]) / 3
//   time_rel = l2norm(mix @ W^T + b)
// One block per hour id, 64 threads (thread j computes output component j).
__global__ void trel_kernel(const float* __restrict__ hour_emb,
                            const float* __restrict__ W,
                            const float* __restrict__ b) {
    int h = blockIdx.x;            // 0..5
    int j = threadIdx.x;           // 0..63
    __shared__ float mix[D];
    __shared__ float red[D];
    int lh = (h - 1 + HP) % HP;
    int nh = (h + 1) % HP;
    mix[j] = (hour_emb[lh * D + j] + hour_emb[h * D + j] + hour_emb[nh * D + j]) * (1.f / 3.f);
    __syncthreads();
    float o = b[j];
    #pragma unroll
    for (int k = 0; k < D; k++)
        o = fmaf(W[j * D + k], mix[k], o);
    red[j] = o * o;
    __syncthreads();
    #pragma unroll
    for (int s = 32; s > 0; s >>= 1) {
        if (j < s) red[j] += red[j + s];
        __syncthreads();
    }
    float nrm = fmaxf(sqrtf(red[0]), 1e-12f);
    g_trel[h * D + j] = o / nrm;
}

// ---------------------------------------------------------------------------
__device__ __forceinline__ float warp_sum(float v) {
    #pragma unroll
    for (int o = 16; o > 0; o >>= 1)
        v += __shfl_xor_sync(0xffffffffu, v, o);
    return v;
}

// ---------------------------------------------------------------------------
// Category graph pass 1: score + denominator. Warp per edge.
__global__ void cat_pass1(const float* __restrict__ cat_emb,
                          const float* __restrict__ rel_emb,
                          const int* __restrict__ csrc,
                          const int* __restrict__ cdst, int ec) {
    int e = (blockIdx.x * blockDim.x + threadIdx.x) >> 5;
    int lane = threadIdx.x & 31;
    if (e >= ec) return;
    int s = csrc[e], d = cdst[e];
    float ssq = 0.f;
    #pragma unroll
    for (int r = 0; r < 2; r++) {
        int j = lane + r * 32;
        float diff = cat_emb[s * D + j] + rel_emb[6 * D + j] - cat_emb[d * D + j];
        ssq = fmaf(diff, diff, ssq);
    }
    ssq = warp_sum(ssq);
    if (lane == 0) {
        float w = __expf(__expf(-ssq));   // exp(score), score = exp(-||diff||^2)
        g_cw[e] = w;
        atomicAdd(&g_cdenom[d], w);
    }
}

// Category graph pass 2: weighted aggregate of h_c into cat_hid.
__global__ void cat_pass2(const float* __restrict__ cat_emb,
                          const int* __restrict__ csrc,
                          const int* __restrict__ cdst,
                          float* __restrict__ cat_hid, int ec) {
    int e = (blockIdx.x * blockDim.x + threadIdx.x) >> 5;
    int lane = threadIdx.x & 31;
    if (e >= ec) return;
    int s = csrc[e], d = cdst[e];
    float coeff = g_cw[e] / g_cdenom[d];
    #pragma unroll
    for (int r = 0; r < 2; r++) {
        int j = lane + r * 32;
        atomicAdd(&cat_hid[d * D + j], cat_emb[s * D + j] * coeff);
    }
}

// ---------------------------------------------------------------------------
// Main graph pass 1: TransH scores + softmax denominator. Warp per edge.
__global__ void main_pass1(const float* __restrict__ nfeat,
                           const float* __restrict__ rel_emb,
                           const float* __restrict__ norm_emb,
                           const int* __restrict__ src,
                           const int* __restrict__ dst,
                           const int* __restrict__ ftype,
                           const int* __restrict__ hourid, int E) {
    int e = (blockIdx.x * blockDim.x + threadIdx.x) >> 5;
    int lane = threadIdx.x & 31;
    if (e >= E) return;
    int s = src[e], d = dst[e], f = ftype[e], h = hourid[e];

    int j0 = lane, j1 = lane + 32;
    float u0 = nfeat[s * D + j0] - nfeat[d * D + j0];
    float u1 = nfeat[s * D + j1] - nfeat[d * D + j1];
    float n0 = norm_emb[f * D + j0], n1 = norm_emb[f * D + j1];
    float tn0 = norm_emb[5 * D + j0], tn1 = norm_emb[5 * D + j1];

    float dot1 = warp_sum(fmaf(u0, n0, u1 * n1));     // <u, norm>
    float dot2 = warp_sum(fmaf(u0, tn0, u1 * tn1));   // <u, time_norm>

    float r0 = rel_emb[f * D + j0], r1 = rel_emb[f * D + j1];
    float tr0 = g_trel[h * D + j0], tr1 = g_trel[h * D + j1];

    float d10 = u0 - dot1 * n0 + r0;
    float d11 = u1 - dot1 * n1 + r1;
    float d20 = u0 - dot2 * tn0 + tr0;
    float d21 = u1 - dot2 * tn1 + tr1;

    float ssq = fmaf(d10, d10, fmaf(d11, d11, fmaf(d20, d20, d21 * d21)));
    ssq = warp_sum(ssq);                               // ssq1 + ssq2

    if (lane == 0) {
        // fin = exp(-ssq1)*exp(-ssq2) = exp(-ssq); softmax weight = exp(fin)
        float w = __expf(__expf(-ssq));
        g_w[e] = w;
        atomicAdd(&g_denom[d], w);
    }
}

// Main graph pass 2: rst[dst] += h * (w / denom[dst])
__global__ void main_pass2(const float* __restrict__ nfeat,
                           const int* __restrict__ src,
                           const int* __restrict__ dst,
                           float* __restrict__ rst, int E) {
    int e = (blockIdx.x * blockDim.x + threadIdx.x) >> 5;
    int lane = threadIdx.x & 31;
    if (e >= E) return;
    int s = src[e], d = dst[e];
    float coeff = g_w[e] / g_denom[d];
    int j0 = lane, j1 = lane + 32;
    atomicAdd(&rst[d * D + j0], nfeat[s * D + j0] * coeff);
    atomicAdd(&rst[d * D + j1], nfeat[s * D + j1] * coeff);
}

// ---------------------------------------------------------------------------
extern "C" void kernel_launch(void* const* d_in, const int* in_sizes, int n_in,
                              void* d_out, int out_size) {
    const float* nfeat      = (const float*)d_in[0];
    const float* cat_emb    = (const float*)d_in[1];
    const float* rel_emb    = (const float*)d_in[2];
    const float* norm_emb   = (const float*)d_in[3];
    const float* hour_emb   = (const float*)d_in[4];
    const float* time_rel_w = (const float*)d_in[5];
    const float* time_rel_b = (const float*)d_in[6];
    const int*   src        = (const int*)d_in[7];
    const int*   dst        = (const int*)d_in[8];
    const int*   ftype      = (const int*)d_in[9];
    const int*   hourid     = (const int*)d_in[10];
    const int*   cat_src    = (const int*)d_in[11];
    const int*   cat_dst    = (const int*)d_in[12];

    const int E  = in_sizes[7];
    const int EC = in_sizes[11];

    float* out     = (float*)d_out;
    float* rst     = out;                       // [N, D]
    float* cat_hid = out + N_NODES * D;         // [NC, D]

    // 1. zero outputs + denominators
    zero_kernel<<<2048, 256>>>(out, out_size);

    // 2. precompute time_rel (6 vectors)
    trel_kernel<<<HP, D>>>(hour_emb, time_rel_w, time_rel_b);

    // 3. category graph (tiny)
    {
        int warps = EC;
        int blocks = (warps * 32 + 255) / 256;
        cat_pass1<<<blocks, 256>>>(cat_emb, rel_emb, cat_src, cat_dst, EC);
        cat_pass2<<<blocks, 256>>>(cat_emb, cat_src, cat_dst, cat_hid, EC);
    }

    // 4. main graph
    {
        int warps = E;
        int blocks = (warps * 32 + 255) / 256;
        main_pass1<<<blocks, 256>>>(nfeat, rel_emb, norm_emb, src, dst, ftype, hourid, E);
        main_pass2<<<blocks, 256>>>(nfeat, src, dst, rst, E);
    }
}

// round 2
// speedup vs baseline: 1.6193x; 1.6193x over previous
#include <cuda_runtime.h>

#define D        64
#define N_NODES  100000
#define E_EDGES  800000
#define NC_NODES 500
#define EC_EDGES 20000
#define HP       6

// Static scratch
__device__ float g_w[E_EDGES];
__device__ float g_cw[EC_EDGES];
__device__ float g_denom[N_NODES];
__device__ float g_cdenom[NC_NODES];
__device__ float g_trel[HP * D];

// ---------------------------------------------------------------------------
__device__ __forceinline__ float warp_sum(float v) {
    #pragma unroll
    for (int o = 16; o > 0; o >>= 1) v += __shfl_xor_sync(0xffffffffu, v, o);
    return v;
}
// Sum over each independent 16-lane half of the warp
__device__ __forceinline__ float half_sum(float v) {
    #pragma unroll
    for (int o = 8; o > 0; o >>= 1) v += __shfl_xor_sync(0xffffffffu, v, o);
    return v;
}
__device__ __forceinline__ void red_add_v4(float* p, float x, float y, float z, float w) {
    asm volatile("red.global.add.v4.f32 [%0], {%1,%2,%3,%4};"
                 :: "l"(p), "f"(x), "f"(y), "f"(z), "f"(w) : "memory");
}

// ---------------------------------------------------------------------------
// Launch 0: zero d_out + denominators; blocks 0..5 also compute time_rel.
__global__ void init_kernel(float* __restrict__ out, int n_out4,
                            const float* __restrict__ hour_emb,
                            const float* __restrict__ W,
                            const float* __restrict__ b) {
    int stride = gridDim.x * blockDim.x;
    float4* out4 = (float4*)out;
    float4 z4 = make_float4(0.f, 0.f, 0.f, 0.f);
    for (int j = blockIdx.x * blockDim.x + threadIdx.x; j < n_out4; j += stride)
        out4[j] = z4;
    for (int j = blockIdx.x * blockDim.x + threadIdx.x; j < N_NODES; j += stride)
        g_denom[j] = 0.f;
    for (int j = blockIdx.x * blockDim.x + threadIdx.x; j < NC_NODES; j += stride)
        g_cdenom[j] = 0.f;

    // time_rel precompute: 6 hour ids, one per block (blocks 0..5)
    if (blockIdx.x < HP) {
        __shared__ float mix[D];
        __shared__ float red[D];
        int h = blockIdx.x;
        int j = threadIdx.x;
        if (j < D) {
            int lh = (h - 1 + HP) % HP, nh = (h + 1) % HP;
            mix[j] = (hour_emb[lh * D + j] + hour_emb[h * D + j] + hour_emb[nh * D + j]) * (1.f / 3.f);
        }
        __syncthreads();
        float o = 0.f;
        if (j < D) {
            o = b[j];
            #pragma unroll
            for (int k = 0; k < D; k++) o = fmaf(W[j * D + k], mix[k], o);
            red[j] = o * o;
        }
        __syncthreads();
        #pragma unroll
        for (int s = 32; s > 0; s >>= 1) {
            if (j < s) red[j] += red[j + s];
            __syncthreads();
        }
        if (j < D) g_trel[h * D + j] = o / fmaxf(sqrtf(red[0]), 1e-12f);
    }
}

// ---------------------------------------------------------------------------
// Launch 1: all pass-1 work (scores + softmax denominators).
//   warp id w < EC              : category edge w   (32 lanes, float2)
//   warp id w >= EC             : main edge pair (w-EC) -> edges 2p, 2p+1
//                                 (16 lanes each, float4)
__global__ void pass1_kernel(const float* __restrict__ nfeat,
                             const float* __restrict__ cat_emb,
                             const float* __restrict__ rel_emb,
                             const float* __restrict__ norm_emb,
                             const int* __restrict__ src,
                             const int* __restrict__ dst,
                             const int* __restrict__ ftype,
                             const int* __restrict__ hourid,
                             const int* __restrict__ csrc,
                             const int* __restrict__ cdst,
                             int E, int EC, int n_warps) {
    int w = (blockIdx.x * blockDim.x + threadIdx.x) >> 5;
    int lane = threadIdx.x & 31;
    if (w >= n_warps) return;

    if (w < EC) {
        // ---- category edge, float2, full-warp reduction
        int e = w;
        int s = csrc[e], d = cdst[e];
        const float2* ce2 = (const float2*)cat_emb;
        const float2* re2 = (const float2*)rel_emb;
        float2 hc = ce2[s * 32 + lane];
        float2 tc = ce2[d * 32 + lane];
        float2 rc = re2[6 * 32 + lane];
        float dx = hc.x + rc.x - tc.x;
        float dy = hc.y + rc.y - tc.y;
        float ssq = warp_sum(fmaf(dx, dx, dy * dy));
        if (lane == 0) {
            float wgt = __expf(__expf(-ssq));
            g_cw[e] = wgt;
            atomicAdd(&g_cdenom[d], wgt);
        }
    } else {
        // ---- main edges: 2 per warp, 16 lanes each, float4
        int p = w - EC;
        int half = lane >> 4;
        int l = lane & 15;
        int e = 2 * p + half;
        if (e >= E) return;
        int s = src[e], d = dst[e], f = ftype[e], h = hourid[e];

        const float4* nf4 = (const float4*)nfeat;
        const float4* nm4 = (const float4*)norm_emb;
        const float4* re4 = (const float4*)rel_emb;
        const float4* tr4 = (const float4*)g_trel;

        float4 a  = nf4[s * 16 + l];
        float4 bb = nf4[d * 16 + l];
        float ux = a.x - bb.x, uy = a.y - bb.y, uz = a.z - bb.z, uw = a.w - bb.w;
        float4 n  = nm4[f * 16 + l];
        float4 tn = nm4[5 * 16 + l];

        float dot1 = half_sum(fmaf(ux, n.x,  fmaf(uy, n.y,  fmaf(uz, n.z,  uw * n.w))));
        float dot2 = half_sum(fmaf(ux, tn.x, fmaf(uy, tn.y, fmaf(uz, tn.z, uw * tn.w))));

        float4 r  = re4[f * 16 + l];
        float4 tr = tr4[h * 16 + l];

        float e1x = ux - dot1 * n.x + r.x;
        float e1y = uy - dot1 * n.y + r.y;
        float e1z = uz - dot1 * n.z + r.z;
        float e1w = uw - dot1 * n.w + r.w;
        float e2x = ux - dot2 * tn.x + tr.x;
        float e2y = uy - dot2 * tn.y + tr.y;
        float e2z = uz - dot2 * tn.z + tr.z;
        float e2w = uw - dot2 * tn.w + tr.w;

        float ssq = half_sum(
            fmaf(e1x, e1x, fmaf(e1y, e1y, fmaf(e1z, e1z, e1w * e1w))) +
            fmaf(e2x, e2x, fmaf(e2y, e2y, fmaf(e2z, e2z, e2w * e2w))));

        if (l == 0) {
            float wgt = __expf(__expf(-ssq));
            g_w[e] = wgt;
            atomicAdd(&g_denom[d], wgt);
        }
    }
}

// ---------------------------------------------------------------------------
// Launch 2: all pass-2 aggregation via vectorized red.global.add.v4.f32.
//   warp id w < EC/2  : category edge pair -> edges 2w, 2w+1 (16 lanes each)
//   warp id w >= EC/2 : main edge pair (w-EC/2)
__global__ void pass2_kernel(const float* __restrict__ nfeat,
                             const float* __restrict__ cat_emb,
                             const int* __restrict__ src,
                             const int* __restrict__ dst,
                             const int* __restrict__ csrc,
                             const int* __restrict__ cdst,
                             float* __restrict__ rst,
                             float* __restrict__ cat_hid,
                             int E, int ECH, int n_warps) {
    int w = (blockIdx.x * blockDim.x + threadIdx.x) >> 5;
    int lane = threadIdx.x & 31;
    if (w >= n_warps) return;
    int half = lane >> 4;
    int l = lane & 15;

    if (w < ECH) {
        int e = 2 * w + half;
        int s = csrc[e], d = cdst[e];
        float coeff = g_cw[e] / g_cdenom[d];
        float4 v = ((const float4*)cat_emb)[s * 16 + l];
        red_add_v4(&cat_hid[d * D + l * 4],
                   v.x * coeff, v.y * coeff, v.z * coeff, v.w * coeff);
    } else {
        int e = 2 * (w - ECH) + half;
        if (e >= E) return;
        int s = src[e], d = dst[e];
        float coeff = g_w[e] / g_denom[d];
        float4 v = ((const float4*)nfeat)[s * 16 + l];
        red_add_v4(&rst[d * D + l * 4],
                   v.x * coeff, v.y * coeff, v.z * coeff, v.w * coeff);
    }
}

// ---------------------------------------------------------------------------
extern "C" void kernel_launch(void* const* d_in, const int* in_sizes, int n_in,
                              void* d_out, int out_size) {
    const float* nfeat      = (const float*)d_in[0];
    const float* cat_emb    = (const float*)d_in[1];
    const float* rel_emb    = (const float*)d_in[2];
    const float* norm_emb   = (const float*)d_in[3];
    const float* hour_emb   = (const float*)d_in[4];
    const float* time_rel_w = (const float*)d_in[5];
    const float* time_rel_b = (const float*)d_in[6];
    const int*   src        = (const int*)d_in[7];
    const int*   dst        = (const int*)d_in[8];
    const int*   ftype      = (const int*)d_in[9];
    const int*   hourid     = (const int*)d_in[10];
    const int*   cat_src    = (const int*)d_in[11];
    const int*   cat_dst    = (const int*)d_in[12];

    const int E  = in_sizes[7];
    const int EC = in_sizes[11];

    float* out     = (float*)d_out;
    float* rst     = out;
    float* cat_hid = out + N_NODES * D;

    // L0: zero + time_rel
    init_kernel<<<1024, 256>>>(out, out_size / 4, hour_emb, time_rel_w, time_rel_b);

    // L1: all pass-1
    {
        int n_warps = EC + (E + 1) / 2;
        int blocks = (n_warps * 32 + 255) / 256;
        pass1_kernel<<<blocks, 256>>>(nfeat, cat_emb, rel_emb, norm_emb,
                                      src, dst, ftype, hourid, cat_src, cat_dst,
                                      E, EC, n_warps);
    }

    // L2: all pass-2
    {
        int ECH = (EC + 1) / 2;
        int n_warps = ECH + (E + 1) / 2;
        int blocks = (n_warps * 32 + 255) / 256;
        pass2_kernel<<<blocks, 256>>>(nfeat, cat_emb, src, dst, cat_src, cat_dst,
                                      rst, cat_hid, E, ECH, n_warps);
    }
}